// round 14
// baseline (speedup 1.0000x reference)
#include <cuda_runtime.h>
#include <cuda_fp16.h>
#include <stdint.h>
#include <math.h>

#define BATCH   4
#define SEQ     4096
#define DMODEL  1024
#define DHEAD   128
#define NPER    (BATCH*SEQ*DHEAD)
#define QSCALE  0.12753102751227150f   // (1/sqrt(128)) * log2(e)
#define NBLOCKS 4.0f

#define XU   (BATCH*SEQ*DMODEL/2)
#define WU   (DHEAD*DMODEL/2)

__device__ uint32_t g_xh[XU];
__device__ uint32_t g_Wh[3*WU];
__device__ uint32_t g_Qp[NPER/2];      // [b*SEQ+row][64 u32]  (Q * QSCALE)
__device__ uint32_t g_Kp[NPER/2];      // [b*SEQ+row][64 u32]
__device__ uint32_t g_Vtp[NPER/2];     // [b][d][SEQ/2 u32]
__device__ float    g_KV[2*NPER];

__device__ __forceinline__ uint32_t smem_u32(const void* p){
    uint32_t a;
    asm("{ .reg .u64 t; cvta.to.shared.u64 t, %1; cvt.u32.u64 %0, t; }" : "=r"(a) : "l"(p));
    return a;
}
__device__ __forceinline__ uint32_t pack2h(float lo, float hi){
    uint32_t r;
    asm("cvt.rn.f16x2.f32 %0, %1, %2;" : "=r"(r) : "f"(hi), "f"(lo));
    return r;
}
__device__ __forceinline__ void mma16(float* c, const uint32_t* a, uint32_t b0, uint32_t b1){
    asm volatile("mma.sync.aligned.m16n8k16.row.col.f32.f16.f16.f32 "
        "{%0,%1,%2,%3}, {%4,%5,%6,%7}, {%8,%9}, {%0,%1,%2,%3};"
        : "+f"(c[0]), "+f"(c[1]), "+f"(c[2]), "+f"(c[3])
        : "r"(a[0]), "r"(a[1]), "r"(a[2]), "r"(a[3]), "r"(b0), "r"(b1));
}
__device__ __forceinline__ void ldsm4(uint32_t& r0, uint32_t& r1, uint32_t& r2,
                                      uint32_t& r3, uint32_t addr){
    asm volatile("ldmatrix.sync.aligned.m8n8.x4.shared.b16 {%0,%1,%2,%3}, [%4];"
        : "=r"(r0), "=r"(r1), "=r"(r2), "=r"(r3) : "r"(addr));
}
#define CP16(dst, src)  asm volatile("cp.async.cg.shared.global [%0], [%1], 16;" :: "r"(dst), "l"(src))
#define CP_COMMIT()     asm volatile("cp.async.commit_group;")
#define CP_WAIT(N)      asm volatile("cp.async.wait_group %0;" :: "n"(N))

// ================= fp32 -> fp16 pre-convert =================
__global__ __launch_bounds__(256) void convert_kernel(
    const float* __restrict__ x,
    const float* __restrict__ Wq, const float* __restrict__ Wk,
    const float* __restrict__ Wv)
{
    const size_t i8 = ((size_t)blockIdx.x * 256 + threadIdx.x) * 8;
    const float* src;
    uint32_t* dst;
    if (i8 < XU) {
        src = x + i8*2;
        dst = g_xh + i8;
    } else {
        const size_t w = i8 - XU;
        const int wi = (int)(w / WU);
        const size_t off = w % WU;
        src = (wi == 0 ? Wq : (wi == 1 ? Wk : Wv)) + off*2;
        dst = g_Wh + (size_t)wi*WU + off;
    }
    uint32_t o[8];
    #pragma unroll
    for (int j = 0; j < 4; j++) {
        float4 v = *(const float4*)(src + j*4);
        o[j*2]   = pack2h(v.x, v.y);
        o[j*2+1] = pack2h(v.z, v.w);
    }
    *(uint4*)dst       = make_uint4(o[0], o[1], o[2], o[3]);
    *(uint4*)(dst + 4) = make_uint4(o[4], o[5], o[6], o[7]);
}

// ================= QKV projection v2 (round-13, proven) =================
#define XRU   36
#define XRU4  (XRU*4)
#define XT_U  (128*XRU)
#define SMEM_PROJ (4*XT_U*4)           // 73728 B
#define NCH   (DMODEL/64)

__global__ __launch_bounds__(256, 2) void proj_kernel(
    const float* __restrict__ bq, const float* __restrict__ bk,
    const float* __restrict__ bv,
    float* Kout, float* Vout)
{
    extern __shared__ uint32_t smu[];
    const int tid  = threadIdx.x;
    const int lane = tid & 31;
    const int warp = tid >> 5;
    const int wm = warp >> 2, wn = warp & 3;
    const int g  = lane >> 2, tg = lane & 3;
    const int lq = lane & 15, lh = lane >> 4;
    const int kl = (lane & 7) + ((lane >> 4) << 3);
    const int kh = (lane >> 3) & 1;

    const int mode = blockIdx.x;
    const int m0   = blockIdx.y * 128;
    const float* bias = (mode == 0 ? bq : (mode == 1 ? bk : bv));

    const uint32_t sb = smem_u32(smu);
    const uint32_t AbA[2] = { sb,            sb + 2*XT_U*4 };
    const uint32_t BbA[2] = { sb + XT_U*4,   sb + 3*XT_U*4 };

    const uint32_t* Ag = g_xh + (size_t)m0 * 512;
    const uint32_t* Bg = g_Wh + (size_t)mode * WU;

    const int cr = tid >> 1, ch = tid & 1;

    float c[4][4][4];
    #pragma unroll
    for (int i=0;i<4;i++) for (int j=0;j<4;j++) for (int k=0;k<4;k++) c[i][j][k]=0.f;

    #pragma unroll
    for (int j = 0; j < 4; j++) {
        CP16(AbA[0] + cr*XRU4 + (ch*4+j)*16, Ag + (size_t)cr*512 + (ch*4+j)*4);
        CP16(BbA[0] + cr*XRU4 + (ch*4+j)*16, Bg + (size_t)cr*512 + (ch*4+j)*4);
    }
    CP_COMMIT();

    #pragma unroll 1
    for (int t = 0; t < NCH; t++) {
        __syncthreads();
        if (t+1 < NCH) {
            const int nb = (t+1) & 1;
            #pragma unroll
            for (int j = 0; j < 4; j++) {
                CP16(AbA[nb] + cr*XRU4 + (ch*4+j)*16,
                     Ag + (size_t)cr*512 + (t+1)*32 + (ch*4+j)*4);
                CP16(BbA[nb] + cr*XRU4 + (ch*4+j)*16,
                     Bg + (size_t)cr*512 + (t+1)*32 + (ch*4+j)*4);
            }
            CP_COMMIT();
            CP_WAIT(1);
        } else {
            CP_WAIT(0);
        }
        __syncthreads();

        const uint32_t Ab = AbA[t&1] + (wm*64 + lq)*XRU4 + lh*16;
        const uint32_t Bb = BbA[t&1] + (wn*32 + kl)*XRU4 + kh*16;
        #pragma unroll
        for (int ks = 0; ks < 4; ks++) {
            uint32_t a[4][4];
            #pragma unroll
            for (int mi = 0; mi < 4; mi++)
                ldsm4(a[mi][0], a[mi][1], a[mi][2], a[mi][3],
                      Ab + mi*16*XRU4 + ks*32);
            #pragma unroll
            for (int nip = 0; nip < 2; nip++) {
                uint32_t r0,r1,r2,r3;
                ldsm4(r0,r1,r2,r3, Bb + nip*16*XRU4 + ks*32);
                #pragma unroll
                for (int mi = 0; mi < 4; mi++) {
                    mma16(c[mi][2*nip],   a[mi], r0, r1);
                    mma16(c[mi][2*nip+1], a[mi], r2, r3);
                }
            }
        }
    }

    const int rowb = m0 + wm*64, colb = wn*32;

    if (mode == 0) {
        #pragma unroll
        for (int mi=0;mi<4;mi++){
            #pragma unroll
            for (int ni=0;ni<4;ni++){
                const int col = colb + ni*8 + 2*tg;
                const float b0 = bias[col], b1 = bias[col+1];
                const int u = (col >> 1);
                g_Qp[(size_t)(rowb + mi*16 + g)    *64 + u] =
                    pack2h((c[mi][ni][0]+b0)*QSCALE, (c[mi][ni][1]+b1)*QSCALE);
                g_Qp[(size_t)(rowb + mi*16 + g + 8)*64 + u] =
                    pack2h((c[mi][ni][2]+b0)*QSCALE, (c[mi][ni][3]+b1)*QSCALE);
            }
        }
        return;
    }

    float* C = (mode == 1 ? Kout : Vout);
    #pragma unroll
    for (int mi=0;mi<4;mi++){
        #pragma unroll
        for (int ni=0;ni<4;ni++){
            const int col = colb + ni*8 + 2*tg;
            const float b0 = bias[col], b1 = bias[col+1];
            float* p0 = C + (size_t)(rowb + mi*16 + g)     * DHEAD + col;
            float* p1 = C + (size_t)(rowb + mi*16 + g + 8) * DHEAD + col;
            *(float2*)p0 = make_float2(c[mi][ni][0]+b0, c[mi][ni][1]+b1);
            *(float2*)p1 = make_float2(c[mi][ni][2]+b0, c[mi][ni][3]+b1);
        }
    }

    if (mode == 1) {
        #pragma unroll
        for (int mi=0;mi<4;mi++){
            #pragma unroll
            for (int ni=0;ni<4;ni++){
                const int col = colb + ni*8 + 2*tg;
                const float b0 = bias[col], b1 = bias[col+1];
                const int u = (col >> 1);
                g_Kp[(size_t)(rowb + mi*16 + g)    *64 + u] =
                    pack2h(c[mi][ni][0]+b0, c[mi][ni][1]+b1);
                g_Kp[(size_t)(rowb + mi*16 + g + 8)*64 + u] =
                    pack2h(c[mi][ni][2]+b0, c[mi][ni][3]+b1);
            }
        }
    } else {
        float* T = (float*)smu;             // [128 d][136]
        __syncthreads();
        #pragma unroll
        for (int mi=0;mi<4;mi++){
            #pragma unroll
            for (int ni=0;ni<4;ni++){
                const int cl = colb + ni*8 + 2*tg;
                const int rl = wm*64 + mi*16 + g;
                const float b0 = bias[cl], b1 = bias[cl+1];
                T[cl*136 + rl]        = c[mi][ni][0]+b0;
                T[(cl+1)*136 + rl]    = c[mi][ni][1]+b1;
                T[cl*136 + rl+8]      = c[mi][ni][2]+b0;
                T[(cl+1)*136 + rl+8]  = c[mi][ni][3]+b1;
            }
        }
        __syncthreads();
        const int bidx = m0 >> 12;
        const int mloc = m0 & (SEQ-1);
        uint32_t* Vtb = g_Vtp + (size_t)bidx*DHEAD*(SEQ/2) + (mloc>>1);
        const int trow = tid >> 1;
        const int th   = tid & 1;
        #pragma unroll
        for (int j=0;j<32;j++){
            const int kk = th*64 + j*2;
            float2 v = *(const float2*)&T[trow*136 + kk];
            Vtb[(size_t)trow*(SEQ/2) + (kk>>1)] = pack2h(v.x, v.y);
        }
    }
}

// ================= fused flash attention (4-warp CTAs, 2 CTA/SM) =========
#define KRU  76
#define VRU  36
#define KRU4 (KRU*4)
#define VRU4 (VRU*4)
#define KS_U (64*KRU)
#define VT_U (128*VRU)
#define NT   (SEQ/64)
#define SMEM_FLASH ((2*KS_U + 2*VT_U)*4)   // 75776 B

__global__ __launch_bounds__(128, 2) void flash_kernel(float* __restrict__ Out)
{
    extern __shared__ uint32_t smu[];
    const int tid  = threadIdx.x;          // 0..127
    const int lane = tid & 31;
    const int warp = tid >> 5;             // 0..3
    const uint32_t sb = smem_u32(smu);
    const uint32_t KsA[2] = { sb, sb + KS_U*4 };
    const uint32_t VtA[2] = { sb + 2*KS_U*4, sb + (2*KS_U+VT_U)*4 };

    const int b  = blockIdx.y;
    const int q0 = blockIdx.x * 64;        // 64 q-rows per CTA
    const uint32_t* Qb = g_Qp + ((size_t)b*SEQ + q0) * 64;
    const uint32_t* Kb = g_Kp + (size_t)b*SEQ*64;
    const uint32_t* Vb = g_Vtp + (size_t)b*DHEAD*(SEQ/2);

    const int g  = lane >> 2;
    const int tg = lane & 3;
    const int lq  = lane & 15;
    const int lh  = lane >> 4;
    const int kl  = (lane & 7) + ((lane >> 4) << 3);
    const int kh  = (lane >> 3) & 1;

    // cp.async mappings (128 threads): K/Q rows 0..63 x 2 half-rows; V row each
    const int kr = tid >> 1, kc = tid & 1;

    // ---- Q fragments: single 64-row staging phase ----
    uint32_t Qf[8][4];
    {
        #pragma unroll
        for (int j = 0; j < 8; j++)
            CP16(KsA[0] + kr*KRU4 + (kc*8+j)*16, Qb + (size_t)kr*64 + (kc*8+j)*4);
        CP_COMMIT();
        CP_WAIT(0);
        __syncthreads();
        const uint32_t qa = KsA[0] + (warp*16 + lq)*KRU4 + lh*16;
        #pragma unroll
        for (int ks = 0; ks < 8; ks++)
            ldsm4(Qf[ks][0], Qf[ks][1], Qf[ks][2], Qf[ks][3], qa + ks*32);
        __syncthreads();                   // Qf read done before K(0) overwrites
    }

    // ---- prologue: K(0), V(0) ----
    #pragma unroll
    for (int j = 0; j < 8; j++)
        CP16(KsA[0] + kr*KRU4 + (kc*8+j)*16, Kb + (size_t)kr*64 + (kc*8+j)*4);
    #pragma unroll
    for (int j = 0; j < 8; j++)
        CP16(VtA[0] + tid*VRU4 + j*16, Vb + (size_t)tid*(SEQ/2) + j*4);
    CP_COMMIT();

    float l0 = 0.f, l1 = 0.f;
    float oa[16][4];
    #pragma unroll
    for (int i=0;i<16;i++){ oa[i][0]=0;oa[i][1]=0;oa[i][2]=0;oa[i][3]=0; }

    const uint32_t kfoff = kl*KRU4 + kh*16;
    const uint32_t vfoff = kl*VRU4 + kh*16;

    #pragma unroll 1
    for (int t = 0; t < NT; t++) {
        __syncthreads();
        if (t+1 < NT) {
            const int nb = (t+1) & 1;
            #pragma unroll
            for (int j = 0; j < 8; j++)
                CP16(KsA[nb] + kr*KRU4 + (kc*8+j)*16,
                     Kb + (size_t)((t+1)*64+kr)*64 + (kc*8+j)*4);
            #pragma unroll
            for (int j = 0; j < 8; j++)
                CP16(VtA[nb] + tid*VRU4 + j*16,
                     Vb + (size_t)tid*(SEQ/2) + (t+1)*32 + j*4);
            CP_COMMIT();
            CP_WAIT(1);
        } else {
            CP_WAIT(0);
        }
        __syncthreads();

        // ---- S(t) = Q K^T ----
        const uint32_t kb = KsA[t&1] + kfoff;
        float sa[8][4];
        #pragma unroll
        for (int i=0;i<8;i++){ sa[i][0]=0;sa[i][1]=0;sa[i][2]=0;sa[i][3]=0; }
        #pragma unroll
        for (int ks = 0; ks < 8; ks++) {
            #pragma unroll
            for (int nip = 0; nip < 4; nip++) {
                uint32_t r0,r1,r2,r3;
                ldsm4(r0,r1,r2,r3, kb + nip*16*KRU4 + ks*32);
                mma16(sa[2*nip],   Qf[ks], r0, r1);
                mma16(sa[2*nip+1], Qf[ks], r2, r3);
            }
        }

        // ---- P = exp2(S) in registers ----
        #pragma unroll
        for (int ni = 0; ni < 8; ni++) {
            sa[ni][0] = exp2f(sa[ni][0]);
            sa[ni][1] = exp2f(sa[ni][1]);
            sa[ni][2] = exp2f(sa[ni][2]);
            sa[ni][3] = exp2f(sa[ni][3]);
            l0 += sa[ni][0] + sa[ni][1];
            l1 += sa[ni][2] + sa[ni][3];
        }

        // ---- O += P V(t) ----
        const uint32_t vb = VtA[t&1] + vfoff;
        #pragma unroll
        for (int ks = 0; ks < 4; ks++) {
            uint32_t a[4];
            a[0] = pack2h(sa[2*ks][0],   sa[2*ks][1]);
            a[1] = pack2h(sa[2*ks][2],   sa[2*ks][3]);
            a[2] = pack2h(sa[2*ks+1][0], sa[2*ks+1][1]);
            a[3] = pack2h(sa[2*ks+1][2], sa[2*ks+1][3]);
            #pragma unroll
            for (int nip = 0; nip < 8; nip++) {
                uint32_t r0,r1,r2,r3;
                ldsm4(r0,r1,r2,r3, vb + nip*16*VRU4 + ks*32);
                mma16(oa[2*nip],   a, r0, r1);
                mma16(oa[2*nip+1], a, r2, r3);
            }
        }
    }

    // ---- epilogue ----
    l0 += __shfl_xor_sync(~0u, l0, 1);  l0 += __shfl_xor_sync(~0u, l0, 2);
    l1 += __shfl_xor_sync(~0u, l1, 1);  l1 += __shfl_xor_sync(~0u, l1, 2);
    const float f0 = NBLOCKS / l0, f1 = NBLOCKS / l1;
    const int qr = q0 + warp*16 + g;
    float* Ob = Out + (size_t)b*SEQ*DHEAD;
    #pragma unroll
    for (int ni = 0; ni < 16; ni++) {
        const int col = ni*8 + 2*tg;
        *(float2*)(Ob + (size_t)qr*DHEAD + col)     = make_float2(oa[ni][0]*f0, oa[ni][1]*f0);
        *(float2*)(Ob + (size_t)(qr+8)*DHEAD + col) = make_float2(oa[ni][2]*f1, oa[ni][3]*f1);
    }
}

// ================= launch =================
extern "C" void kernel_launch(void* const* d_in, const int* in_sizes, int n_in,
                              void* d_out, int out_size)
{
    const float* x  = (const float*)d_in[0];
    const float* Wq = (const float*)d_in[1];
    const float* bq = (const float*)d_in[2];
    const float* Wk = (const float*)d_in[3];
    const float* bk = (const float*)d_in[4];
    const float* Wv = (const float*)d_in[5];
    const float* bv = (const float*)d_in[6];

    float* out = (float*)d_out;
    float* gkv;
    cudaGetSymbolAddress((void**)&gkv, g_KV);

    float *Kout, *Vout;
    if (out_size >= 3 * NPER) { Kout = out + NPER; Vout = out + 2 * NPER; }
    else                      { Kout = gkv;        Vout = gkv + NPER;     }

    cudaFuncSetAttribute(proj_kernel,  cudaFuncAttributeMaxDynamicSharedMemorySize, SMEM_PROJ);
    cudaFuncSetAttribute(flash_kernel, cudaFuncAttributeMaxDynamicSharedMemorySize, SMEM_FLASH);

    convert_kernel<<<(XU + 3*WU) / (256*8), 256>>>(x, Wq, Wk, Wv);
    proj_kernel<<<dim3(3, 128, 1), 256, SMEM_PROJ>>>(bq, bk, bv, Kout, Vout);
    flash_kernel<<<dim3(SEQ/64, BATCH), 128, SMEM_FLASH>>>(out);
}

// round 15
// speedup vs baseline: 1.2899x; 1.2899x over previous
#include <cuda_runtime.h>
#include <cuda_fp16.h>
#include <stdint.h>
#include <math.h>

#define BATCH   4
#define SEQ     4096
#define DMODEL  1024
#define DHEAD   128
#define NPER    (BATCH*SEQ*DHEAD)
#define QSCALE  0.12753102751227150f   // (1/sqrt(128)) * log2(e)
#define NBLOCKS 4.0f

#define XU   (BATCH*SEQ*DMODEL/2)
#define WU   (DHEAD*DMODEL/2)

__device__ uint32_t g_xh[XU];
__device__ uint32_t g_Wh[3*WU];
__device__ uint32_t g_Qp[NPER/2];      // [b*SEQ+row][64 u32]  (Q * QSCALE)
__device__ uint32_t g_Kp[NPER/2];      // [b*SEQ+row][64 u32]
__device__ uint32_t g_Vtp[NPER/2];     // [b][d][SEQ/2 u32]
__device__ float    g_KV[2*NPER];

__device__ __forceinline__ uint32_t smem_u32(const void* p){
    uint32_t a;
    asm("{ .reg .u64 t; cvta.to.shared.u64 t, %1; cvt.u32.u64 %0, t; }" : "=r"(a) : "l"(p));
    return a;
}
__device__ __forceinline__ uint32_t pack2h(float lo, float hi){
    uint32_t r;
    asm("cvt.rn.f16x2.f32 %0, %1, %2;" : "=r"(r) : "f"(hi), "f"(lo));
    return r;
}
__device__ __forceinline__ void mma16(float* c, const uint32_t* a, uint32_t b0, uint32_t b1){
    asm volatile("mma.sync.aligned.m16n8k16.row.col.f32.f16.f16.f32 "
        "{%0,%1,%2,%3}, {%4,%5,%6,%7}, {%8,%9}, {%0,%1,%2,%3};"
        : "+f"(c[0]), "+f"(c[1]), "+f"(c[2]), "+f"(c[3])
        : "r"(a[0]), "r"(a[1]), "r"(a[2]), "r"(a[3]), "r"(b0), "r"(b1));
}
__device__ __forceinline__ void ldsm4(uint32_t& r0, uint32_t& r1, uint32_t& r2,
                                      uint32_t& r3, uint32_t addr){
    asm volatile("ldmatrix.sync.aligned.m8n8.x4.shared.b16 {%0,%1,%2,%3}, [%4];"
        : "=r"(r0), "=r"(r1), "=r"(r2), "=r"(r3) : "r"(addr));
}
#define CP16(dst, src)  asm volatile("cp.async.cg.shared.global [%0], [%1], 16;" :: "r"(dst), "l"(src))
#define CP_COMMIT()     asm volatile("cp.async.commit_group;")
#define CP_WAIT(N)      asm volatile("cp.async.wait_group %0;" :: "n"(N))

// ================= fp32 -> fp16 pre-convert =================
__global__ __launch_bounds__(256) void convert_kernel(
    const float* __restrict__ x,
    const float* __restrict__ Wq, const float* __restrict__ Wk,
    const float* __restrict__ Wv)
{
    const size_t i8 = ((size_t)blockIdx.x * 256 + threadIdx.x) * 8;
    const float* src;
    uint32_t* dst;
    if (i8 < XU) {
        src = x + i8*2;
        dst = g_xh + i8;
    } else {
        const size_t w = i8 - XU;
        const int wi = (int)(w / WU);
        const size_t off = w % WU;
        src = (wi == 0 ? Wq : (wi == 1 ? Wk : Wv)) + off*2;
        dst = g_Wh + (size_t)wi*WU + off;
    }
    uint32_t o[8];
    #pragma unroll
    for (int j = 0; j < 4; j++) {
        float4 v = *(const float4*)(src + j*4);
        o[j*2]   = pack2h(v.x, v.y);
        o[j*2+1] = pack2h(v.z, v.w);
    }
    *(uint4*)dst       = make_uint4(o[0], o[1], o[2], o[3]);
    *(uint4*)(dst + 4) = make_uint4(o[4], o[5], o[6], o[7]);
}

// ================= QKV projection v2 (round-13, proven) =================
#define XRU   36
#define XRU4  (XRU*4)
#define XT_U  (128*XRU)
#define SMEM_PROJ (4*XT_U*4)           // 73728 B
#define NCH   (DMODEL/64)

__global__ __launch_bounds__(256, 2) void proj_kernel(
    const float* __restrict__ bq, const float* __restrict__ bk,
    const float* __restrict__ bv,
    float* Kout, float* Vout)
{
    extern __shared__ uint32_t smu[];
    const int tid  = threadIdx.x;
    const int lane = tid & 31;
    const int warp = tid >> 5;
    const int wm = warp >> 2, wn = warp & 3;
    const int g  = lane >> 2, tg = lane & 3;
    const int lq = lane & 15, lh = lane >> 4;
    const int kl = (lane & 7) + ((lane >> 4) << 3);
    const int kh = (lane >> 3) & 1;

    const int mode = blockIdx.x;
    const int m0   = blockIdx.y * 128;
    const float* bias = (mode == 0 ? bq : (mode == 1 ? bk : bv));

    const uint32_t sb = smem_u32(smu);
    const uint32_t AbA[2] = { sb,            sb + 2*XT_U*4 };
    const uint32_t BbA[2] = { sb + XT_U*4,   sb + 3*XT_U*4 };

    const uint32_t* Ag = g_xh + (size_t)m0 * 512;
    const uint32_t* Bg = g_Wh + (size_t)mode * WU;

    const int cr = tid >> 1, ch = tid & 1;

    float c[4][4][4];
    #pragma unroll
    for (int i=0;i<4;i++) for (int j=0;j<4;j++) for (int k=0;k<4;k++) c[i][j][k]=0.f;

    #pragma unroll
    for (int j = 0; j < 4; j++) {
        CP16(AbA[0] + cr*XRU4 + (ch*4+j)*16, Ag + (size_t)cr*512 + (ch*4+j)*4);
        CP16(BbA[0] + cr*XRU4 + (ch*4+j)*16, Bg + (size_t)cr*512 + (ch*4+j)*4);
    }
    CP_COMMIT();

    #pragma unroll 1
    for (int t = 0; t < NCH; t++) {
        __syncthreads();
        if (t+1 < NCH) {
            const int nb = (t+1) & 1;
            #pragma unroll
            for (int j = 0; j < 4; j++) {
                CP16(AbA[nb] + cr*XRU4 + (ch*4+j)*16,
                     Ag + (size_t)cr*512 + (t+1)*32 + (ch*4+j)*4);
                CP16(BbA[nb] + cr*XRU4 + (ch*4+j)*16,
                     Bg + (size_t)cr*512 + (t+1)*32 + (ch*4+j)*4);
            }
            CP_COMMIT();
            CP_WAIT(1);
        } else {
            CP_WAIT(0);
        }
        __syncthreads();

        const uint32_t Ab = AbA[t&1] + (wm*64 + lq)*XRU4 + lh*16;
        const uint32_t Bb = BbA[t&1] + (wn*32 + kl)*XRU4 + kh*16;
        #pragma unroll
        for (int ks = 0; ks < 4; ks++) {
            uint32_t a[4][4];
            #pragma unroll
            for (int mi = 0; mi < 4; mi++)
                ldsm4(a[mi][0], a[mi][1], a[mi][2], a[mi][3],
                      Ab + mi*16*XRU4 + ks*32);
            #pragma unroll
            for (int nip = 0; nip < 2; nip++) {
                uint32_t r0,r1,r2,r3;
                ldsm4(r0,r1,r2,r3, Bb + nip*16*XRU4 + ks*32);
                #pragma unroll
                for (int mi = 0; mi < 4; mi++) {
                    mma16(c[mi][2*nip],   a[mi], r0, r1);
                    mma16(c[mi][2*nip+1], a[mi], r2, r3);
                }
            }
        }
    }

    const int rowb = m0 + wm*64, colb = wn*32;

    if (mode == 0) {
        #pragma unroll
        for (int mi=0;mi<4;mi++){
            #pragma unroll
            for (int ni=0;ni<4;ni++){
                const int col = colb + ni*8 + 2*tg;
                const float b0 = bias[col], b1 = bias[col+1];
                const int u = (col >> 1);
                g_Qp[(size_t)(rowb + mi*16 + g)    *64 + u] =
                    pack2h((c[mi][ni][0]+b0)*QSCALE, (c[mi][ni][1]+b1)*QSCALE);
                g_Qp[(size_t)(rowb + mi*16 + g + 8)*64 + u] =
                    pack2h((c[mi][ni][2]+b0)*QSCALE, (c[mi][ni][3]+b1)*QSCALE);
            }
        }
        return;
    }

    float* C = (mode == 1 ? Kout : Vout);
    #pragma unroll
    for (int mi=0;mi<4;mi++){
        #pragma unroll
        for (int ni=0;ni<4;ni++){
            const int col = colb + ni*8 + 2*tg;
            const float b0 = bias[col], b1 = bias[col+1];
            float* p0 = C + (size_t)(rowb + mi*16 + g)     * DHEAD + col;
            float* p1 = C + (size_t)(rowb + mi*16 + g + 8) * DHEAD + col;
            *(float2*)p0 = make_float2(c[mi][ni][0]+b0, c[mi][ni][1]+b1);
            *(float2*)p1 = make_float2(c[mi][ni][2]+b0, c[mi][ni][3]+b1);
        }
    }

    if (mode == 1) {
        #pragma unroll
        for (int mi=0;mi<4;mi++){
            #pragma unroll
            for (int ni=0;ni<4;ni++){
                const int col = colb + ni*8 + 2*tg;
                const float b0 = bias[col], b1 = bias[col+1];
                const int u = (col >> 1);
                g_Kp[(size_t)(rowb + mi*16 + g)    *64 + u] =
                    pack2h(c[mi][ni][0]+b0, c[mi][ni][1]+b1);
                g_Kp[(size_t)(rowb + mi*16 + g + 8)*64 + u] =
                    pack2h(c[mi][ni][2]+b0, c[mi][ni][3]+b1);
            }
        }
    } else {
        float* T = (float*)smu;             // [128 d][136]
        __syncthreads();
        #pragma unroll
        for (int mi=0;mi<4;mi++){
            #pragma unroll
            for (int ni=0;ni<4;ni++){
                const int cl = colb + ni*8 + 2*tg;
                const int rl = wm*64 + mi*16 + g;
                const float b0 = bias[cl], b1 = bias[cl+1];
                T[cl*136 + rl]        = c[mi][ni][0]+b0;
                T[(cl+1)*136 + rl]    = c[mi][ni][1]+b1;
                T[cl*136 + rl+8]      = c[mi][ni][2]+b0;
                T[(cl+1)*136 + rl+8]  = c[mi][ni][3]+b1;
            }
        }
        __syncthreads();
        const int bidx = m0 >> 12;
        const int mloc = m0 & (SEQ-1);
        uint32_t* Vtb = g_Vtp + (size_t)bidx*DHEAD*(SEQ/2) + (mloc>>1);
        const int trow = tid >> 1;
        const int th   = tid & 1;
        #pragma unroll
        for (int j=0;j<32;j++){
            const int kk = th*64 + j*2;
            float2 v = *(const float2*)&T[trow*136 + kk];
            Vtb[(size_t)trow*(SEQ/2) + (kk>>1)] = pack2h(v.x, v.y);
        }
    }
}

// ====== fused flash attention (8 warps, 3-stage ring, 1 barrier/iter) ======
#define KRU  76
#define VRU  36
#define KRU4 (KRU*4)
#define VRU4 (VRU*4)
#define KS_U (64*KRU)
#define VT_U (128*VRU)
#define NT   (SEQ/64)
#define SMEM_FLASH (3*(KS_U + VT_U)*4)   // 113664 B

__global__ __launch_bounds__(256, 1) void flash_kernel(float* __restrict__ Out)
{
    extern __shared__ uint32_t smu[];
    const int tid  = threadIdx.x;
    const int lane = tid & 31;
    const int warp = tid >> 5;
    const uint32_t sb = smem_u32(smu);
    uint32_t KsA[3], VtA[3];
    #pragma unroll
    for (int i = 0; i < 3; i++) {
        KsA[i] = sb + (uint32_t)i*(KS_U+VT_U)*4;
        VtA[i] = KsA[i] + KS_U*4;
    }

    const int b  = blockIdx.y;
    const int q0 = blockIdx.x * 128;
    const uint32_t* Qb = g_Qp + ((size_t)b*SEQ + q0) * 64;
    const uint32_t* Kb = g_Kp + (size_t)b*SEQ*64;
    const uint32_t* Vb = g_Vtp + (size_t)b*DHEAD*(SEQ/2);

    const int g  = lane >> 2;
    const int tg = lane & 3;
    const int lq  = lane & 15;
    const int lh  = lane >> 4;
    const int kl  = (lane & 7) + ((lane >> 4) << 3);
    const int kh  = (lane >> 3) & 1;

    const int kr = tid >> 2, kc = tid & 3;
    const int vd = tid >> 1, vh = tid & 1;

    // ---- Q fragments (staged through Ks buf0) ----
    uint32_t Qf[8][4];
    #pragma unroll 1
    for (int ph = 0; ph < 2; ph++) {
        #pragma unroll
        for (int j = 0; j < 4; j++)
            CP16(KsA[0] + kr*KRU4 + (kc*4+j)*16,
                 Qb + (size_t)(ph*64+kr)*64 + (kc*4+j)*4);
        CP_COMMIT();
        CP_WAIT(0);
        __syncthreads();
        if ((warp >> 2) == ph) {
            const uint32_t qa = KsA[0] + ((warp&3)*16 + lq)*KRU4 + lh*16;
            #pragma unroll
            for (int ks = 0; ks < 8; ks++)
                ldsm4(Qf[ks][0], Qf[ks][1], Qf[ks][2], Qf[ks][3], qa + ks*32);
        }
        __syncthreads();
    }

    // ---- prologue: tiles 0 and 1 into bufs 0, 1 ----
    #pragma unroll
    for (int p = 0; p < 2; p++) {
        #pragma unroll
        for (int j = 0; j < 4; j++)
            CP16(KsA[p] + kr*KRU4 + (kc*4+j)*16,
                 Kb + (size_t)(p*64+kr)*64 + (kc*4+j)*4);
        #pragma unroll
        for (int j = 0; j < 4; j++)
            CP16(VtA[p] + vd*VRU4 + (vh*4+j)*16,
                 Vb + (size_t)vd*(SEQ/2) + p*32 + (vh*4+j)*4);
        CP_COMMIT();
    }

    float l0 = 0.f, l1 = 0.f;
    float oa[16][4];
    #pragma unroll
    for (int i=0;i<16;i++){ oa[i][0]=0;oa[i][1]=0;oa[i][2]=0;oa[i][3]=0; }

    const uint32_t kfoff = kl*KRU4 + kh*16;
    const uint32_t vfoff = kl*VRU4 + kh*16;

    int cb = 0, nbuf = 2;                 // current buf, buf for tile t+2
    #pragma unroll 1
    for (int t = 0; t < NT; t++) {
        if (t+1 < NT) { CP_WAIT(1); } else { CP_WAIT(0); }
        __syncthreads();                  // tile t visible; buf nbuf free

        if (t+2 < NT) {                   // issue tile t+2 into nbuf
            #pragma unroll
            for (int j = 0; j < 4; j++)
                CP16(KsA[nbuf] + kr*KRU4 + (kc*4+j)*16,
                     Kb + (size_t)((t+2)*64+kr)*64 + (kc*4+j)*4);
            #pragma unroll
            for (int j = 0; j < 4; j++)
                CP16(VtA[nbuf] + vd*VRU4 + (vh*4+j)*16,
                     Vb + (size_t)vd*(SEQ/2) + (t+2)*32 + (vh*4+j)*4);
            CP_COMMIT();
        }

        // ---- S(t) = Q K^T ----
        const uint32_t kb = KsA[cb] + kfoff;
        float sa[8][4];
        #pragma unroll
        for (int i=0;i<8;i++){ sa[i][0]=0;sa[i][1]=0;sa[i][2]=0;sa[i][3]=0; }
        #pragma unroll
        for (int ks = 0; ks < 8; ks++) {
            #pragma unroll
            for (int nip = 0; nip < 4; nip++) {
                uint32_t r0,r1,r2,r3;
                ldsm4(r0,r1,r2,r3, kb + nip*16*KRU4 + ks*32);
                mma16(sa[2*nip],   Qf[ks], r0, r1);
                mma16(sa[2*nip+1], Qf[ks], r2, r3);
            }
        }

        // ---- interleaved exp + PV: per ks-block, exp feeds its own MMAs ----
        const uint32_t vb = VtA[cb] + vfoff;
        #pragma unroll
        for (int ks = 0; ks < 4; ks++) {
            const float p0 = exp2f(sa[2*ks][0]);
            const float p1 = exp2f(sa[2*ks][1]);
            const float p2 = exp2f(sa[2*ks][2]);
            const float p3 = exp2f(sa[2*ks][3]);
            const float p4 = exp2f(sa[2*ks+1][0]);
            const float p5 = exp2f(sa[2*ks+1][1]);
            const float p6 = exp2f(sa[2*ks+1][2]);
            const float p7 = exp2f(sa[2*ks+1][3]);
            l0 += p0 + p1 + p4 + p5;
            l1 += p2 + p3 + p6 + p7;
            uint32_t a[4];
            a[0] = pack2h(p0, p1);
            a[1] = pack2h(p2, p3);
            a[2] = pack2h(p4, p5);
            a[3] = pack2h(p6, p7);
            #pragma unroll
            for (int nip = 0; nip < 8; nip++) {
                uint32_t r0,r1,r2,r3;
                ldsm4(r0,r1,r2,r3, vb + nip*16*VRU4 + ks*32);
                mma16(oa[2*nip],   a, r0, r1);
                mma16(oa[2*nip+1], a, r2, r3);
            }
        }

        cb = (cb == 2) ? 0 : cb + 1;
        nbuf = (nbuf == 2) ? 0 : nbuf + 1;
    }

    // ---- epilogue ----
    l0 += __shfl_xor_sync(~0u, l0, 1);  l0 += __shfl_xor_sync(~0u, l0, 2);
    l1 += __shfl_xor_sync(~0u, l1, 1);  l1 += __shfl_xor_sync(~0u, l1, 2);
    const float f0 = NBLOCKS / l0, f1 = NBLOCKS / l1;
    const int qr = q0 + warp*16 + g;
    float* Ob = Out + (size_t)b*SEQ*DHEAD;
    #pragma unroll
    for (int ni = 0; ni < 16; ni++) {
        const int col = ni*8 + 2*tg;
        *(float2*)(Ob + (size_t)qr*DHEAD + col)     = make_float2(oa[ni][0]*f0, oa[ni][1]*f0);
        *(float2*)(Ob + (size_t)(qr+8)*DHEAD + col) = make_float2(oa[ni][2]*f1, oa[ni][3]*f1);
    }
}

// ================= launch =================
extern "C" void kernel_launch(void* const* d_in, const int* in_sizes, int n_in,
                              void* d_out, int out_size)
{
    const float* x  = (const float*)d_in[0];
    const float* Wq = (const float*)d_in[1];
    const float* bq = (const float*)d_in[2];
    const float* Wk = (const float*)d_in[3];
    const float* bk = (const float*)d_in[4];
    const float* Wv = (const float*)d_in[5];
    const float* bv = (const float*)d_in[6];

    float* out = (float*)d_out;
    float* gkv;
    cudaGetSymbolAddress((void**)&gkv, g_KV);

    float *Kout, *Vout;
    if (out_size >= 3 * NPER) { Kout = out + NPER; Vout = out + 2 * NPER; }
    else                      { Kout = gkv;        Vout = gkv + NPER;     }

    cudaFuncSetAttribute(proj_kernel,  cudaFuncAttributeMaxDynamicSharedMemorySize, SMEM_PROJ);
    cudaFuncSetAttribute(flash_kernel, cudaFuncAttributeMaxDynamicSharedMemorySize, SMEM_FLASH);

    convert_kernel<<<(XU + 3*WU) / (256*8), 256>>>(x, Wq, Wk, Wv);
    proj_kernel<<<dim3(3, 128, 1), 256, SMEM_PROJ>>>(bq, bk, bv, Kout, Vout);
    flash_kernel<<<dim3(SEQ/128, BATCH), 256, SMEM_FLASH>>>(out);
}

// round 16
// speedup vs baseline: 1.3025x; 1.0098x over previous
#include <cuda_runtime.h>
#include <cuda_fp16.h>
#include <stdint.h>
#include <math.h>

#define BATCH   4
#define SEQ     4096
#define DMODEL  1024
#define DHEAD   128
#define NPER    (BATCH*SEQ*DHEAD)
#define QSCALE  0.12753102751227150f   // (1/sqrt(128)) * log2(e)
#define NBLOCKS 4.0f

#define XU   (BATCH*SEQ*DMODEL/2)
#define WU   (DHEAD*DMODEL/2)

__device__ uint32_t g_xh[XU];
__device__ uint32_t g_Wh[3*WU];
__device__ uint32_t g_Qp[NPER/2];      // [b*SEQ+row][64 u32]  (Q * QSCALE)
__device__ uint32_t g_Kp[NPER/2];      // [b*SEQ+row][64 u32]
__device__ uint32_t g_Vtp[NPER/2];     // [b][d][SEQ/2 u32]
__device__ float    g_KV[2*NPER];

__device__ __forceinline__ uint32_t smem_u32(const void* p){
    uint32_t a;
    asm("{ .reg .u64 t; cvta.to.shared.u64 t, %1; cvt.u32.u64 %0, t; }" : "=r"(a) : "l"(p));
    return a;
}
__device__ __forceinline__ uint32_t pack2h(float lo, float hi){
    uint32_t r;
    asm("cvt.rn.f16x2.f32 %0, %1, %2;" : "=r"(r) : "f"(hi), "f"(lo));
    return r;
}
__device__ __forceinline__ void mma16(float* c, const uint32_t* a, uint32_t b0, uint32_t b1){
    asm volatile("mma.sync.aligned.m16n8k16.row.col.f32.f16.f16.f32 "
        "{%0,%1,%2,%3}, {%4,%5,%6,%7}, {%8,%9}, {%0,%1,%2,%3};"
        : "+f"(c[0]), "+f"(c[1]), "+f"(c[2]), "+f"(c[3])
        : "r"(a[0]), "r"(a[1]), "r"(a[2]), "r"(a[3]), "r"(b0), "r"(b1));
}
__device__ __forceinline__ void ldsm4(uint32_t& r0, uint32_t& r1, uint32_t& r2,
                                      uint32_t& r3, uint32_t addr){
    asm volatile("ldmatrix.sync.aligned.m8n8.x4.shared.b16 {%0,%1,%2,%3}, [%4];"
        : "=r"(r0), "=r"(r1), "=r"(r2), "=r"(r3) : "r"(addr));
}
#define CP16(dst, src)  asm volatile("cp.async.cg.shared.global [%0], [%1], 16;" :: "r"(dst), "l"(src))
#define CP_COMMIT()     asm volatile("cp.async.commit_group;")
#define CP_WAIT(N)      asm volatile("cp.async.wait_group %0;" :: "n"(N))

// ================= fp32 -> fp16 pre-convert =================
__global__ __launch_bounds__(256) void convert_kernel(
    const float* __restrict__ x,
    const float* __restrict__ Wq, const float* __restrict__ Wk,
    const float* __restrict__ Wv)
{
    const size_t i8 = ((size_t)blockIdx.x * 256 + threadIdx.x) * 8;
    const float* src;
    uint32_t* dst;
    if (i8 < XU) {
        src = x + i8*2;
        dst = g_xh + i8;
    } else {
        const size_t w = i8 - XU;
        const int wi = (int)(w / WU);
        const size_t off = w % WU;
        src = (wi == 0 ? Wq : (wi == 1 ? Wk : Wv)) + off*2;
        dst = g_Wh + (size_t)wi*WU + off;
    }
    uint32_t o[8];
    #pragma unroll
    for (int j = 0; j < 4; j++) {
        float4 v = *(const float4*)(src + j*4);
        o[j*2]   = pack2h(v.x, v.y);
        o[j*2+1] = pack2h(v.z, v.w);
    }
    *(uint4*)dst       = make_uint4(o[0], o[1], o[2], o[3]);
    *(uint4*)(dst + 4) = make_uint4(o[4], o[5], o[6], o[7]);
}

// ================= QKV projection v2 (round-13, proven) =================
#define XRU   36
#define XRU4  (XRU*4)
#define XT_U  (128*XRU)
#define SMEM_PROJ (4*XT_U*4)           // 73728 B
#define NCH   (DMODEL/64)

__global__ __launch_bounds__(256, 2) void proj_kernel(
    const float* __restrict__ bq, const float* __restrict__ bk,
    const float* __restrict__ bv,
    float* Kout, float* Vout)
{
    extern __shared__ uint32_t smu[];
    const int tid  = threadIdx.x;
    const int lane = tid & 31;
    const int warp = tid >> 5;
    const int wm = warp >> 2, wn = warp & 3;
    const int g  = lane >> 2, tg = lane & 3;
    const int lq = lane & 15, lh = lane >> 4;
    const int kl = (lane & 7) + ((lane >> 4) << 3);
    const int kh = (lane >> 3) & 1;

    const int mode = blockIdx.x;
    const int m0   = blockIdx.y * 128;
    const float* bias = (mode == 0 ? bq : (mode == 1 ? bk : bv));

    const uint32_t sb = smem_u32(smu);
    const uint32_t AbA[2] = { sb,            sb + 2*XT_U*4 };
    const uint32_t BbA[2] = { sb + XT_U*4,   sb + 3*XT_U*4 };

    const uint32_t* Ag = g_xh + (size_t)m0 * 512;
    const uint32_t* Bg = g_Wh + (size_t)mode * WU;

    const int cr = tid >> 1, ch = tid & 1;

    float c[4][4][4];
    #pragma unroll
    for (int i=0;i<4;i++) for (int j=0;j<4;j++) for (int k=0;k<4;k++) c[i][j][k]=0.f;

    #pragma unroll
    for (int j = 0; j < 4; j++) {
        CP16(AbA[0] + cr*XRU4 + (ch*4+j)*16, Ag + (size_t)cr*512 + (ch*4+j)*4);
        CP16(BbA[0] + cr*XRU4 + (ch*4+j)*16, Bg + (size_t)cr*512 + (ch*4+j)*4);
    }
    CP_COMMIT();

    #pragma unroll 1
    for (int t = 0; t < NCH; t++) {
        __syncthreads();
        if (t+1 < NCH) {
            const int nb = (t+1) & 1;
            #pragma unroll
            for (int j = 0; j < 4; j++) {
                CP16(AbA[nb] + cr*XRU4 + (ch*4+j)*16,
                     Ag + (size_t)cr*512 + (t+1)*32 + (ch*4+j)*4);
                CP16(BbA[nb] + cr*XRU4 + (ch*4+j)*16,
                     Bg + (size_t)cr*512 + (t+1)*32 + (ch*4+j)*4);
            }
            CP_COMMIT();
            CP_WAIT(1);
        } else {
            CP_WAIT(0);
        }
        __syncthreads();

        const uint32_t Ab = AbA[t&1] + (wm*64 + lq)*XRU4 + lh*16;
        const uint32_t Bb = BbA[t&1] + (wn*32 + kl)*XRU4 + kh*16;
        #pragma unroll
        for (int ks = 0; ks < 4; ks++) {
            uint32_t a[4][4];
            #pragma unroll
            for (int mi = 0; mi < 4; mi++)
                ldsm4(a[mi][0], a[mi][1], a[mi][2], a[mi][3],
                      Ab + mi*16*XRU4 + ks*32);
            #pragma unroll
            for (int nip = 0; nip < 2; nip++) {
                uint32_t r0,r1,r2,r3;
                ldsm4(r0,r1,r2,r3, Bb + nip*16*XRU4 + ks*32);
                #pragma unroll
                for (int mi = 0; mi < 4; mi++) {
                    mma16(c[mi][2*nip],   a[mi], r0, r1);
                    mma16(c[mi][2*nip+1], a[mi], r2, r3);
                }
            }
        }
    }

    const int rowb = m0 + wm*64, colb = wn*32;

    if (mode == 0) {
        #pragma unroll
        for (int mi=0;mi<4;mi++){
            #pragma unroll
            for (int ni=0;ni<4;ni++){
                const int col = colb + ni*8 + 2*tg;
                const float b0 = bias[col], b1 = bias[col+1];
                const int u = (col >> 1);
                g_Qp[(size_t)(rowb + mi*16 + g)    *64 + u] =
                    pack2h((c[mi][ni][0]+b0)*QSCALE, (c[mi][ni][1]+b1)*QSCALE);
                g_Qp[(size_t)(rowb + mi*16 + g + 8)*64 + u] =
                    pack2h((c[mi][ni][2]+b0)*QSCALE, (c[mi][ni][3]+b1)*QSCALE);
            }
        }
        return;
    }

    float* C = (mode == 1 ? Kout : Vout);
    #pragma unroll
    for (int mi=0;mi<4;mi++){
        #pragma unroll
        for (int ni=0;ni<4;ni++){
            const int col = colb + ni*8 + 2*tg;
            const float b0 = bias[col], b1 = bias[col+1];
            float* p0 = C + (size_t)(rowb + mi*16 + g)     * DHEAD + col;
            float* p1 = C + (size_t)(rowb + mi*16 + g + 8) * DHEAD + col;
            *(float2*)p0 = make_float2(c[mi][ni][0]+b0, c[mi][ni][1]+b1);
            *(float2*)p1 = make_float2(c[mi][ni][2]+b0, c[mi][ni][3]+b1);
        }
    }

    if (mode == 1) {
        #pragma unroll
        for (int mi=0;mi<4;mi++){
            #pragma unroll
            for (int ni=0;ni<4;ni++){
                const int col = colb + ni*8 + 2*tg;
                const float b0 = bias[col], b1 = bias[col+1];
                const int u = (col >> 1);
                g_Kp[(size_t)(rowb + mi*16 + g)    *64 + u] =
                    pack2h(c[mi][ni][0]+b0, c[mi][ni][1]+b1);
                g_Kp[(size_t)(rowb + mi*16 + g + 8)*64 + u] =
                    pack2h(c[mi][ni][2]+b0, c[mi][ni][3]+b1);
            }
        }
    } else {
        float* T = (float*)smu;             // [128 d][136]
        __syncthreads();
        #pragma unroll
        for (int mi=0;mi<4;mi++){
            #pragma unroll
            for (int ni=0;ni<4;ni++){
                const int cl = colb + ni*8 + 2*tg;
                const int rl = wm*64 + mi*16 + g;
                const float b0 = bias[cl], b1 = bias[cl+1];
                T[cl*136 + rl]        = c[mi][ni][0]+b0;
                T[(cl+1)*136 + rl]    = c[mi][ni][1]+b1;
                T[cl*136 + rl+8]      = c[mi][ni][2]+b0;
                T[(cl+1)*136 + rl+8]  = c[mi][ni][3]+b1;
            }
        }
        __syncthreads();
        const int bidx = m0 >> 12;
        const int mloc = m0 & (SEQ-1);
        uint32_t* Vtb = g_Vtp + (size_t)bidx*DHEAD*(SEQ/2) + (mloc>>1);
        const int trow = tid >> 1;
        const int th   = tid & 1;
        #pragma unroll
        for (int j=0;j<32;j++){
            const int kk = th*64 + j*2;
            float2 v = *(const float2*)&T[trow*136 + kk];
            Vtb[(size_t)trow*(SEQ/2) + (kk>>1)] = pack2h(v.x, v.y);
        }
    }
}

// ====== flash attention: cross-iteration pipeline S(t+1) || PV(t) ======
#define KRU  76
#define VRU  36
#define KRU4 (KRU*4)
#define VRU4 (VRU*4)
#define KS_U (64*KRU)
#define VT_U (128*VRU)
#define NT   (SEQ/64)
#define SMEM_FLASH (3*(KS_U + VT_U)*4)   // 113664 B

__global__ __launch_bounds__(256, 1) void flash_kernel(float* __restrict__ Out)
{
    extern __shared__ uint32_t smu[];
    const int tid  = threadIdx.x;
    const int lane = tid & 31;
    const int warp = tid >> 5;
    const uint32_t sb = smem_u32(smu);
    uint32_t KsA[3], VtA[3];
    #pragma unroll
    for (int i = 0; i < 3; i++) {
        KsA[i] = sb + (uint32_t)i*(KS_U+VT_U)*4;
        VtA[i] = KsA[i] + KS_U*4;
    }

    const int b  = blockIdx.y;
    const int q0 = blockIdx.x * 128;
    const uint32_t* Qb = g_Qp + ((size_t)b*SEQ + q0) * 64;
    const uint32_t* Kb = g_Kp + (size_t)b*SEQ*64;
    const uint32_t* Vb = g_Vtp + (size_t)b*DHEAD*(SEQ/2);

    const int g  = lane >> 2;
    const int tg = lane & 3;
    const int lq  = lane & 15;
    const int lh  = lane >> 4;
    const int kl  = (lane & 7) + ((lane >> 4) << 3);
    const int kh  = (lane >> 3) & 1;

    const int kr = tid >> 2, kc = tid & 3;
    const int vd = tid >> 1, vh = tid & 1;

    // ---- Q fragments (staged through Ks buf0) ----
    uint32_t Qf[8][4];
    #pragma unroll 1
    for (int ph = 0; ph < 2; ph++) {
        #pragma unroll
        for (int j = 0; j < 4; j++)
            CP16(KsA[0] + kr*KRU4 + (kc*4+j)*16,
                 Qb + (size_t)(ph*64+kr)*64 + (kc*4+j)*4);
        CP_COMMIT();
        CP_WAIT(0);
        __syncthreads();
        if ((warp >> 2) == ph) {
            const uint32_t qa = KsA[0] + ((warp&3)*16 + lq)*KRU4 + lh*16;
            #pragma unroll
            for (int ks = 0; ks < 8; ks++)
                ldsm4(Qf[ks][0], Qf[ks][1], Qf[ks][2], Qf[ks][3], qa + ks*32);
        }
        __syncthreads();
    }

    // ---- prologue: tiles 0 and 1 as separate groups ----
    #pragma unroll
    for (int p = 0; p < 2; p++) {
        #pragma unroll
        for (int j = 0; j < 4; j++)
            CP16(KsA[p] + kr*KRU4 + (kc*4+j)*16,
                 Kb + (size_t)(p*64+kr)*64 + (kc*4+j)*4);
        #pragma unroll
        for (int j = 0; j < 4; j++)
            CP16(VtA[p] + vd*VRU4 + (vh*4+j)*16,
                 Vb + (size_t)vd*(SEQ/2) + p*32 + (vh*4+j)*4);
        CP_COMMIT();
    }

    float l0 = 0.f, l1 = 0.f;
    float oa[16][4];
    #pragma unroll
    for (int i=0;i<16;i++){ oa[i][0]=0;oa[i][1]=0;oa[i][2]=0;oa[i][3]=0; }

    const uint32_t kfoff = kl*KRU4 + kh*16;
    const uint32_t vfoff = kl*VRU4 + kh*16;

    // ---- pre-loop: S(0) from buf0 ----
    float sa[8][4];
    #pragma unroll
    for (int i=0;i<8;i++){ sa[i][0]=0;sa[i][1]=0;sa[i][2]=0;sa[i][3]=0; }
    {
        CP_WAIT(1);                     // tile 0 complete
        __syncthreads();
        const uint32_t kb0 = KsA[0] + kfoff;
        #pragma unroll
        for (int ks = 0; ks < 8; ks++) {
            #pragma unroll
            for (int nip = 0; nip < 4; nip++) {
                uint32_t r0,r1,r2,r3;
                ldsm4(r0,r1,r2,r3, kb0 + nip*16*KRU4 + ks*32);
                mma16(sa[2*nip],   Qf[ks], r0, r1);
                mma16(sa[2*nip+1], Qf[ks], r2, r3);
            }
        }
    }

    #pragma unroll 1
    for (int t = 0; t < NT; t++) {
        // tile t+1 (K for S(t+1)) must be complete; buf (t+2)%3 free to refill
        CP_WAIT(0);
        __syncthreads();
        if (t+2 < NT) {
            const int nb3 = (t+2) % 3;
            #pragma unroll
            for (int j = 0; j < 4; j++)
                CP16(KsA[nb3] + kr*KRU4 + (kc*4+j)*16,
                     Kb + (size_t)((t+2)*64+kr)*64 + (kc*4+j)*4);
            #pragma unroll
            for (int j = 0; j < 4; j++)
                CP16(VtA[nb3] + vd*VRU4 + (vh*4+j)*16,
                     Vb + (size_t)vd*(SEQ/2) + (t+2)*32 + (vh*4+j)*4);
            CP_COMMIT();
        }

        // ---- exp(S(t)) -> packed A-fragments; free sa for S(t+1) ----
        uint32_t a[4][4];
        #pragma unroll
        for (int ks = 0; ks < 4; ks++) {
            const float p0 = exp2f(sa[2*ks][0]);
            const float p1 = exp2f(sa[2*ks][1]);
            const float p2 = exp2f(sa[2*ks][2]);
            const float p3 = exp2f(sa[2*ks][3]);
            const float p4 = exp2f(sa[2*ks+1][0]);
            const float p5 = exp2f(sa[2*ks+1][1]);
            const float p6 = exp2f(sa[2*ks+1][2]);
            const float p7 = exp2f(sa[2*ks+1][3]);
            l0 += p0 + p1 + p4 + p5;
            l1 += p2 + p3 + p6 + p7;
            a[ks][0] = pack2h(p0, p1);
            a[ks][1] = pack2h(p2, p3);
            a[ks][2] = pack2h(p4, p5);
            a[ks][3] = pack2h(p6, p7);
        }
        #pragma unroll
        for (int i=0;i<8;i++){ sa[i][0]=0;sa[i][1]=0;sa[i][2]=0;sa[i][3]=0; }

        // ---- interleaved: S(t+1) (K from buf (t+1)%3) || PV(t) (V from buf t%3) ----
        const uint32_t kbN = KsA[(t+1)%3] + kfoff;
        const uint32_t vbC = VtA[t%3] + vfoff;
        const bool more = (t+1 < NT);
        #pragma unroll
        for (int ks = 0; ks < 8; ks++) {
            if (more) {
                #pragma unroll
                for (int nip = 0; nip < 4; nip++) {
                    uint32_t r0,r1,r2,r3;
                    ldsm4(r0,r1,r2,r3, kbN + nip*16*KRU4 + ks*32);
                    mma16(sa[2*nip],   Qf[ks], r0, r1);
                    mma16(sa[2*nip+1], Qf[ks], r2, r3);
                }
            }
            if ((ks & 1) == 0) {
                const int pk = ks >> 1;
                #pragma unroll
                for (int nip = 0; nip < 8; nip++) {
                    uint32_t r0,r1,r2,r3;
                    ldsm4(r0,r1,r2,r3, vbC + nip*16*VRU4 + pk*32);
                    mma16(oa[2*nip],   a[pk], r0, r1);
                    mma16(oa[2*nip+1], a[pk], r2, r3);
                }
            }
        }
    }

    // ---- epilogue ----
    l0 += __shfl_xor_sync(~0u, l0, 1);  l0 += __shfl_xor_sync(~0u, l0, 2);
    l1 += __shfl_xor_sync(~0u, l1, 1);  l1 += __shfl_xor_sync(~0u, l1, 2);
    const float f0 = NBLOCKS / l0, f1 = NBLOCKS / l1;
    const int qr = q0 + warp*16 + g;
    float* Ob = Out + (size_t)b*SEQ*DHEAD;
    #pragma unroll
    for (int ni = 0; ni < 16; ni++) {
        const int col = ni*8 + 2*tg;
        *(float2*)(Ob + (size_t)qr*DHEAD + col)     = make_float2(oa[ni][0]*f0, oa[ni][1]*f0);
        *(float2*)(Ob + (size_t)(qr+8)*DHEAD + col) = make_float2(oa[ni][2]*f1, oa[ni][3]*f1);
    }
}

// ================= launch =================
extern "C" void kernel_launch(void* const* d_in, const int* in_sizes, int n_in,
                              void* d_out, int out_size)
{
    const float* x  = (const float*)d_in[0];
    const float* Wq = (const float*)d_in[1];
    const float* bq = (const float*)d_in[2];
    const float* Wk = (const float*)d_in[3];
    const float* bk = (const float*)d_in[4];
    const float* Wv = (const float*)d_in[5];
    const float* bv = (const float*)d_in[6];

    float* out = (float*)d_out;
    float* gkv;
    cudaGetSymbolAddress((void**)&gkv, g_KV);

    float *Kout, *Vout;
    if (out_size >= 3 * NPER) { Kout = out + NPER; Vout = out + 2 * NPER; }
    else                      { Kout = gkv;        Vout = gkv + NPER;     }

    cudaFuncSetAttribute(proj_kernel,  cudaFuncAttributeMaxDynamicSharedMemorySize, SMEM_PROJ);
    cudaFuncSetAttribute(flash_kernel, cudaFuncAttributeMaxDynamicSharedMemorySize, SMEM_FLASH);

    convert_kernel<<<(XU + 3*WU) / (256*8), 256>>>(x, Wq, Wk, Wv);
    proj_kernel<<<dim3(3, 128, 1), 256, SMEM_PROJ>>>(bq, bk, bv, Kout, Vout);
    flash_kernel<<<dim3(SEQ/128, BATCH), 256, SMEM_FLASH>>>(out);
}

// round 17
// speedup vs baseline: 1.3164x; 1.0106x over previous
#include <cuda_runtime.h>
#include <cuda_fp16.h>
#include <stdint.h>
#include <math.h>

#define BATCH   4
#define SEQ     4096
#define DMODEL  1024
#define DHEAD   128
#define NPER    (BATCH*SEQ*DHEAD)
#define QSCALE  0.12753102751227150f   // (1/sqrt(128)) * log2(e)
#define NBLOCKS 4.0f

#define XU   (BATCH*SEQ*DMODEL/2)
#define WU   (DHEAD*DMODEL/2)

__device__ uint32_t g_xh[XU];
__device__ uint32_t g_Wh[3*WU];
__device__ uint32_t g_Qp[NPER/2];      // [b*SEQ+row][64 u32]  (Q * QSCALE)
__device__ uint32_t g_Kp[NPER/2];      // [b*SEQ+row][64 u32]
__device__ uint32_t g_Vtp[NPER/2];     // [b][d][SEQ/2 u32]
__device__ float    g_KV[2*NPER];

__device__ __forceinline__ uint32_t smem_u32(const void* p){
    uint32_t a;
    asm("{ .reg .u64 t; cvta.to.shared.u64 t, %1; cvt.u32.u64 %0, t; }" : "=r"(a) : "l"(p));
    return a;
}
__device__ __forceinline__ uint32_t pack2h(float lo, float hi){
    uint32_t r;
    asm("cvt.rn.f16x2.f32 %0, %1, %2;" : "=r"(r) : "f"(hi), "f"(lo));
    return r;
}
__device__ __forceinline__ void mma16(float* c, const uint32_t* a, uint32_t b0, uint32_t b1){
    asm volatile("mma.sync.aligned.m16n8k16.row.col.f32.f16.f16.f32 "
        "{%0,%1,%2,%3}, {%4,%5,%6,%7}, {%8,%9}, {%0,%1,%2,%3};"
        : "+f"(c[0]), "+f"(c[1]), "+f"(c[2]), "+f"(c[3])
        : "r"(a[0]), "r"(a[1]), "r"(a[2]), "r"(a[3]), "r"(b0), "r"(b1));
}
__device__ __forceinline__ void ldsm4(uint32_t& r0, uint32_t& r1, uint32_t& r2,
                                      uint32_t& r3, uint32_t addr){
    asm volatile("ldmatrix.sync.aligned.m8n8.x4.shared.b16 {%0,%1,%2,%3}, [%4];"
        : "=r"(r0), "=r"(r1), "=r"(r2), "=r"(r3) : "r"(addr));
}
#define CP16(dst, src)  asm volatile("cp.async.cg.shared.global [%0], [%1], 16;" :: "r"(dst), "l"(src))
#define CP_COMMIT()     asm volatile("cp.async.commit_group;")
#define CP_WAIT(N)      asm volatile("cp.async.wait_group %0;" :: "n"(N))

// ================= fp32 -> fp16 pre-convert =================
__global__ __launch_bounds__(256) void convert_kernel(
    const float* __restrict__ x,
    const float* __restrict__ Wq, const float* __restrict__ Wk,
    const float* __restrict__ Wv)
{
    const size_t i8 = ((size_t)blockIdx.x * 256 + threadIdx.x) * 8;
    const float* src;
    uint32_t* dst;
    if (i8 < XU) {
        src = x + i8*2;
        dst = g_xh + i8;
    } else {
        const size_t w = i8 - XU;
        const int wi = (int)(w / WU);
        const size_t off = w % WU;
        src = (wi == 0 ? Wq : (wi == 1 ? Wk : Wv)) + off*2;
        dst = g_Wh + (size_t)wi*WU + off;
    }
    uint32_t o[8];
    #pragma unroll
    for (int j = 0; j < 4; j++) {
        float4 v = *(const float4*)(src + j*4);
        o[j*2]   = pack2h(v.x, v.y);
        o[j*2+1] = pack2h(v.z, v.w);
    }
    *(uint4*)dst       = make_uint4(o[0], o[1], o[2], o[3]);
    *(uint4*)(dst + 4) = make_uint4(o[4], o[5], o[6], o[7]);
}

// ================= shared proj constants =================
#define XRU   36
#define XRU4  (XRU*4)
#define XT_U  (128*XRU)
#define NCH   (DMODEL/64)
#define SMEM_Q  (4*XT_U*4)             // 73728 B (A,B double-buffered)
#define SMEM_KV (6*XT_U*4)             // 110592 B (A,Bk,Bv double-buffered)

// ================= Q projection (grid 128, single wave) =================
__global__ __launch_bounds__(256, 2) void proj_q_kernel(const float* __restrict__ bq)
{
    extern __shared__ uint32_t smu[];
    const int tid  = threadIdx.x;
    const int lane = tid & 31;
    const int warp = tid >> 5;
    const int wm = warp >> 2, wn = warp & 3;
    const int g  = lane >> 2, tg = lane & 3;
    const int lq = lane & 15, lh = lane >> 4;
    const int kl = (lane & 7) + ((lane >> 4) << 3);
    const int kh = (lane >> 3) & 1;

    const int m0 = blockIdx.x * 128;
    const uint32_t sb = smem_u32(smu);
    const uint32_t AbA[2] = { sb,            sb + 2*XT_U*4 };
    const uint32_t BbA[2] = { sb + XT_U*4,   sb + 3*XT_U*4 };

    const uint32_t* Ag = g_xh + (size_t)m0 * 512;
    const uint32_t* Bg = g_Wh;                       // Wq

    const int cr = tid >> 1, ch = tid & 1;

    float c[4][4][4];
    #pragma unroll
    for (int i=0;i<4;i++) for (int j=0;j<4;j++) for (int k=0;k<4;k++) c[i][j][k]=0.f;

    #pragma unroll
    for (int j = 0; j < 4; j++) {
        CP16(AbA[0] + cr*XRU4 + (ch*4+j)*16, Ag + (size_t)cr*512 + (ch*4+j)*4);
        CP16(BbA[0] + cr*XRU4 + (ch*4+j)*16, Bg + (size_t)cr*512 + (ch*4+j)*4);
    }
    CP_COMMIT();

    #pragma unroll 1
    for (int t = 0; t < NCH; t++) {
        __syncthreads();
        if (t+1 < NCH) {
            const int nb = (t+1) & 1;
            #pragma unroll
            for (int j = 0; j < 4; j++) {
                CP16(AbA[nb] + cr*XRU4 + (ch*4+j)*16,
                     Ag + (size_t)cr*512 + (t+1)*32 + (ch*4+j)*4);
                CP16(BbA[nb] + cr*XRU4 + (ch*4+j)*16,
                     Bg + (size_t)cr*512 + (t+1)*32 + (ch*4+j)*4);
            }
            CP_COMMIT();
            CP_WAIT(1);
        } else {
            CP_WAIT(0);
        }
        __syncthreads();

        const uint32_t Ab = AbA[t&1] + (wm*64 + lq)*XRU4 + lh*16;
        const uint32_t Bb = BbA[t&1] + (wn*32 + kl)*XRU4 + kh*16;
        #pragma unroll
        for (int ks = 0; ks < 4; ks++) {
            uint32_t a[4][4];
            #pragma unroll
            for (int mi = 0; mi < 4; mi++)
                ldsm4(a[mi][0], a[mi][1], a[mi][2], a[mi][3],
                      Ab + mi*16*XRU4 + ks*32);
            #pragma unroll
            for (int nip = 0; nip < 2; nip++) {
                uint32_t r0,r1,r2,r3;
                ldsm4(r0,r1,r2,r3, Bb + nip*16*XRU4 + ks*32);
                #pragma unroll
                for (int mi = 0; mi < 4; mi++) {
                    mma16(c[mi][2*nip],   a[mi], r0, r1);
                    mma16(c[mi][2*nip+1], a[mi], r2, r3);
                }
            }
        }
    }

    const int rowb = m0 + wm*64, colb = wn*32;
    #pragma unroll
    for (int mi=0;mi<4;mi++){
        #pragma unroll
        for (int ni=0;ni<4;ni++){
            const int col = colb + ni*8 + 2*tg;
            const float b0 = bq[col], b1 = bq[col+1];
            const int u = (col >> 1);
            g_Qp[(size_t)(rowb + mi*16 + g)    *64 + u] =
                pack2h((c[mi][ni][0]+b0)*QSCALE, (c[mi][ni][1]+b1)*QSCALE);
            g_Qp[(size_t)(rowb + mi*16 + g + 8)*64 + u] =
                pack2h((c[mi][ni][2]+b0)*QSCALE, (c[mi][ni][3]+b1)*QSCALE);
        }
    }
}

// ========== KV projection (grid 128, dual accumulators, shared A) ==========
__global__ __launch_bounds__(256) void proj_kv_kernel(
    const float* __restrict__ bk, const float* __restrict__ bv,
    float* Kout, float* Vout)
{
    extern __shared__ uint32_t smu[];
    const int tid  = threadIdx.x;
    const int lane = tid & 31;
    const int warp = tid >> 5;
    const int wm = warp >> 2, wn = warp & 3;
    const int g  = lane >> 2, tg = lane & 3;
    const int lq = lane & 15, lh = lane >> 4;
    const int kl = (lane & 7) + ((lane >> 4) << 3);
    const int kh = (lane >> 3) & 1;

    const int m0 = blockIdx.x * 128;
    const uint32_t sb = smem_u32(smu);
    const uint32_t AbA[2]  = { sb,              sb + 3*XT_U*4 };
    const uint32_t BkA[2]  = { sb +   XT_U*4,   sb + 4*XT_U*4 };
    const uint32_t BvA[2]  = { sb + 2*XT_U*4,   sb + 5*XT_U*4 };

    const uint32_t* Ag  = g_xh + (size_t)m0 * 512;
    const uint32_t* Bkg = g_Wh + (size_t)1*WU;
    const uint32_t* Bvg = g_Wh + (size_t)2*WU;

    const int cr = tid >> 1, ch = tid & 1;

    float ck[4][4][4], cv[4][4][4];
    #pragma unroll
    for (int i=0;i<4;i++) for (int j=0;j<4;j++) for (int k=0;k<4;k++){ ck[i][j][k]=0.f; cv[i][j][k]=0.f; }

    #pragma unroll
    for (int j = 0; j < 4; j++) {
        CP16(AbA[0] + cr*XRU4 + (ch*4+j)*16, Ag  + (size_t)cr*512 + (ch*4+j)*4);
        CP16(BkA[0] + cr*XRU4 + (ch*4+j)*16, Bkg + (size_t)cr*512 + (ch*4+j)*4);
        CP16(BvA[0] + cr*XRU4 + (ch*4+j)*16, Bvg + (size_t)cr*512 + (ch*4+j)*4);
    }
    CP_COMMIT();

    #pragma unroll 1
    for (int t = 0; t < NCH; t++) {
        __syncthreads();
        if (t+1 < NCH) {
            const int nb = (t+1) & 1;
            #pragma unroll
            for (int j = 0; j < 4; j++) {
                CP16(AbA[nb] + cr*XRU4 + (ch*4+j)*16,
                     Ag  + (size_t)cr*512 + (t+1)*32 + (ch*4+j)*4);
                CP16(BkA[nb] + cr*XRU4 + (ch*4+j)*16,
                     Bkg + (size_t)cr*512 + (t+1)*32 + (ch*4+j)*4);
                CP16(BvA[nb] + cr*XRU4 + (ch*4+j)*16,
                     Bvg + (size_t)cr*512 + (t+1)*32 + (ch*4+j)*4);
            }
            CP_COMMIT();
            CP_WAIT(1);
        } else {
            CP_WAIT(0);
        }
        __syncthreads();

        const uint32_t Ab  = AbA[t&1] + (wm*64 + lq)*XRU4 + lh*16;
        const uint32_t Bbk = BkA[t&1] + (wn*32 + kl)*XRU4 + kh*16;
        const uint32_t Bbv = BvA[t&1] + (wn*32 + kl)*XRU4 + kh*16;
        #pragma unroll
        for (int ks = 0; ks < 4; ks++) {
            uint32_t a[4][4];
            #pragma unroll
            for (int mi = 0; mi < 4; mi++)
                ldsm4(a[mi][0], a[mi][1], a[mi][2], a[mi][3],
                      Ab + mi*16*XRU4 + ks*32);
            #pragma unroll
            for (int nip = 0; nip < 2; nip++) {
                uint32_t r0,r1,r2,r3;
                ldsm4(r0,r1,r2,r3, Bbk + nip*16*XRU4 + ks*32);
                #pragma unroll
                for (int mi = 0; mi < 4; mi++) {
                    mma16(ck[mi][2*nip],   a[mi], r0, r1);
                    mma16(ck[mi][2*nip+1], a[mi], r2, r3);
                }
                uint32_t s0,s1,s2,s3;
                ldsm4(s0,s1,s2,s3, Bbv + nip*16*XRU4 + ks*32);
                #pragma unroll
                for (int mi = 0; mi < 4; mi++) {
                    mma16(cv[mi][2*nip],   a[mi], s0, s1);
                    mma16(cv[mi][2*nip+1], a[mi], s2, s3);
                }
            }
        }
    }

    const int rowb = m0 + wm*64, colb = wn*32;

    // ---- K epilogue: fp32 K + fp16 Kp ----
    #pragma unroll
    for (int mi=0;mi<4;mi++){
        #pragma unroll
        for (int ni=0;ni<4;ni++){
            const int col = colb + ni*8 + 2*tg;
            const float b0 = bk[col], b1 = bk[col+1];
            float* p0 = Kout + (size_t)(rowb + mi*16 + g)     * DHEAD + col;
            float* p1 = Kout + (size_t)(rowb + mi*16 + g + 8) * DHEAD + col;
            *(float2*)p0 = make_float2(ck[mi][ni][0]+b0, ck[mi][ni][1]+b1);
            *(float2*)p1 = make_float2(ck[mi][ni][2]+b0, ck[mi][ni][3]+b1);
            const int u = (col >> 1);
            g_Kp[(size_t)(rowb + mi*16 + g)    *64 + u] =
                pack2h(ck[mi][ni][0]+b0, ck[mi][ni][1]+b1);
            g_Kp[(size_t)(rowb + mi*16 + g + 8)*64 + u] =
                pack2h(ck[mi][ni][2]+b0, ck[mi][ni][3]+b1);
        }
    }

    // ---- V epilogue: fp32 V + transposed fp16 Vt ----
    #pragma unroll
    for (int mi=0;mi<4;mi++){
        #pragma unroll
        for (int ni=0;ni<4;ni++){
            const int col = colb + ni*8 + 2*tg;
            const float b0 = bv[col], b1 = bv[col+1];
            float* p0 = Vout + (size_t)(rowb + mi*16 + g)     * DHEAD + col;
            float* p1 = Vout + (size_t)(rowb + mi*16 + g + 8) * DHEAD + col;
            *(float2*)p0 = make_float2(cv[mi][ni][0]+b0, cv[mi][ni][1]+b1);
            *(float2*)p1 = make_float2(cv[mi][ni][2]+b0, cv[mi][ni][3]+b1);
        }
    }
    {
        float* T = (float*)smu;             // [128 d][136]
        __syncthreads();
        #pragma unroll
        for (int mi=0;mi<4;mi++){
            #pragma unroll
            for (int ni=0;ni<4;ni++){
                const int cl = colb + ni*8 + 2*tg;
                const int rl = wm*64 + mi*16 + g;
                const float b0 = bv[cl], b1 = bv[cl+1];
                T[cl*136 + rl]        = cv[mi][ni][0]+b0;
                T[(cl+1)*136 + rl]    = cv[mi][ni][1]+b1;
                T[cl*136 + rl+8]      = cv[mi][ni][2]+b0;
                T[(cl+1)*136 + rl+8]  = cv[mi][ni][3]+b1;
            }
        }
        __syncthreads();
        const int bidx = m0 >> 12;
        const int mloc = m0 & (SEQ-1);
        uint32_t* Vtb = g_Vtp + (size_t)bidx*DHEAD*(SEQ/2) + (mloc>>1);
        const int trow = tid >> 1;
        const int th   = tid & 1;
        #pragma unroll
        for (int j=0;j<32;j++){
            const int kk = th*64 + j*2;
            float2 v = *(const float2*)&T[trow*136 + kk];
            Vtb[(size_t)trow*(SEQ/2) + (kk>>1)] = pack2h(v.x, v.y);
        }
    }
}

// ====== flash attention (round-16, best known) ======
#define KRU  76
#define VRU  36
#define KRU4 (KRU*4)
#define VRU4 (VRU*4)
#define KS_U (64*KRU)
#define VT_U (128*VRU)
#define NT   (SEQ/64)
#define SMEM_FLASH (3*(KS_U + VT_U)*4)   // 113664 B

__global__ __launch_bounds__(256, 1) void flash_kernel(float* __restrict__ Out)
{
    extern __shared__ uint32_t smu[];
    const int tid  = threadIdx.x;
    const int lane = tid & 31;
    const int warp = tid >> 5;
    const uint32_t sb = smem_u32(smu);
    uint32_t KsA[3], VtA[3];
    #pragma unroll
    for (int i = 0; i < 3; i++) {
        KsA[i] = sb + (uint32_t)i*(KS_U+VT_U)*4;
        VtA[i] = KsA[i] + KS_U*4;
    }

    const int b  = blockIdx.y;
    const int q0 = blockIdx.x * 128;
    const uint32_t* Qb = g_Qp + ((size_t)b*SEQ + q0) * 64;
    const uint32_t* Kb = g_Kp + (size_t)b*SEQ*64;
    const uint32_t* Vb = g_Vtp + (size_t)b*DHEAD*(SEQ/2);

    const int g  = lane >> 2;
    const int tg = lane & 3;
    const int lq  = lane & 15;
    const int lh  = lane >> 4;
    const int kl  = (lane & 7) + ((lane >> 4) << 3);
    const int kh  = (lane >> 3) & 1;

    const int kr = tid >> 2, kc = tid & 3;
    const int vd = tid >> 1, vh = tid & 1;

    uint32_t Qf[8][4];
    #pragma unroll 1
    for (int ph = 0; ph < 2; ph++) {
        #pragma unroll
        for (int j = 0; j < 4; j++)
            CP16(KsA[0] + kr*KRU4 + (kc*4+j)*16,
                 Qb + (size_t)(ph*64+kr)*64 + (kc*4+j)*4);
        CP_COMMIT();
        CP_WAIT(0);
        __syncthreads();
        if ((warp >> 2) == ph) {
            const uint32_t qa = KsA[0] + ((warp&3)*16 + lq)*KRU4 + lh*16;
            #pragma unroll
            for (int ks = 0; ks < 8; ks++)
                ldsm4(Qf[ks][0], Qf[ks][1], Qf[ks][2], Qf[ks][3], qa + ks*32);
        }
        __syncthreads();
    }

    #pragma unroll
    for (int p = 0; p < 2; p++) {
        #pragma unroll
        for (int j = 0; j < 4; j++)
            CP16(KsA[p] + kr*KRU4 + (kc*4+j)*16,
                 Kb + (size_t)(p*64+kr)*64 + (kc*4+j)*4);
        #pragma unroll
        for (int j = 0; j < 4; j++)
            CP16(VtA[p] + vd*VRU4 + (vh*4+j)*16,
                 Vb + (size_t)vd*(SEQ/2) + p*32 + (vh*4+j)*4);
        CP_COMMIT();
    }

    float l0 = 0.f, l1 = 0.f;
    float oa[16][4];
    #pragma unroll
    for (int i=0;i<16;i++){ oa[i][0]=0;oa[i][1]=0;oa[i][2]=0;oa[i][3]=0; }

    const uint32_t kfoff = kl*KRU4 + kh*16;
    const uint32_t vfoff = kl*VRU4 + kh*16;

    float sa[8][4];
    #pragma unroll
    for (int i=0;i<8;i++){ sa[i][0]=0;sa[i][1]=0;sa[i][2]=0;sa[i][3]=0; }
    {
        CP_WAIT(1);
        __syncthreads();
        const uint32_t kb0 = KsA[0] + kfoff;
        #pragma unroll
        for (int ks = 0; ks < 8; ks++) {
            #pragma unroll
            for (int nip = 0; nip < 4; nip++) {
                uint32_t r0,r1,r2,r3;
                ldsm4(r0,r1,r2,r3, kb0 + nip*16*KRU4 + ks*32);
                mma16(sa[2*nip],   Qf[ks], r0, r1);
                mma16(sa[2*nip+1], Qf[ks], r2, r3);
            }
        }
    }

    #pragma unroll 1
    for (int t = 0; t < NT; t++) {
        CP_WAIT(0);
        __syncthreads();
        if (t+2 < NT) {
            const int nb3 = (t+2) % 3;
            #pragma unroll
            for (int j = 0; j < 4; j++)
                CP16(KsA[nb3] + kr*KRU4 + (kc*4+j)*16,
                     Kb + (size_t)((t+2)*64+kr)*64 + (kc*4+j)*4);
            #pragma unroll
            for (int j = 0; j < 4; j++)
                CP16(VtA[nb3] + vd*VRU4 + (vh*4+j)*16,
                     Vb + (size_t)vd*(SEQ/2) + (t+2)*32 + (vh*4+j)*4);
            CP_COMMIT();
        }

        uint32_t a[4][4];
        #pragma unroll
        for (int ks = 0; ks < 4; ks++) {
            const float p0 = exp2f(sa[2*ks][0]);
            const float p1 = exp2f(sa[2*ks][1]);
            const float p2 = exp2f(sa[2*ks][2]);
            const float p3 = exp2f(sa[2*ks][3]);
            const float p4 = exp2f(sa[2*ks+1][0]);
            const float p5 = exp2f(sa[2*ks+1][1]);
            const float p6 = exp2f(sa[2*ks+1][2]);
            const float p7 = exp2f(sa[2*ks+1][3]);
            l0 += p0 + p1 + p4 + p5;
            l1 += p2 + p3 + p6 + p7;
            a[ks][0] = pack2h(p0, p1);
            a[ks][1] = pack2h(p2, p3);
            a[ks][2] = pack2h(p4, p5);
            a[ks][3] = pack2h(p6, p7);
        }
        #pragma unroll
        for (int i=0;i<8;i++){ sa[i][0]=0;sa[i][1]=0;sa[i][2]=0;sa[i][3]=0; }

        const uint32_t kbN = KsA[(t+1)%3] + kfoff;
        const uint32_t vbC = VtA[t%3] + vfoff;
        const bool more = (t+1 < NT);
        #pragma unroll
        for (int ks = 0; ks < 8; ks++) {
            if (more) {
                #pragma unroll
                for (int nip = 0; nip < 4; nip++) {
                    uint32_t r0,r1,r2,r3;
                    ldsm4(r0,r1,r2,r3, kbN + nip*16*KRU4 + ks*32);
                    mma16(sa[2*nip],   Qf[ks], r0, r1);
                    mma16(sa[2*nip+1], Qf[ks], r2, r3);
                }
            }
            if ((ks & 1) == 0) {
                const int pk = ks >> 1;
                #pragma unroll
                for (int nip = 0; nip < 8; nip++) {
                    uint32_t r0,r1,r2,r3;
                    ldsm4(r0,r1,r2,r3, vbC + nip*16*VRU4 + pk*32);
                    mma16(oa[2*nip],   a[pk], r0, r1);
                    mma16(oa[2*nip+1], a[pk], r2, r3);
                }
            }
        }
    }

    l0 += __shfl_xor_sync(~0u, l0, 1);  l0 += __shfl_xor_sync(~0u, l0, 2);
    l1 += __shfl_xor_sync(~0u, l1, 1);  l1 += __shfl_xor_sync(~0u, l1, 2);
    const float f0 = NBLOCKS / l0, f1 = NBLOCKS / l1;
    const int qr = q0 + warp*16 + g;
    float* Ob = Out + (size_t)b*SEQ*DHEAD;
    #pragma unroll
    for (int ni = 0; ni < 16; ni++) {
        const int col = ni*8 + 2*tg;
        *(float2*)(Ob + (size_t)qr*DHEAD + col)     = make_float2(oa[ni][0]*f0, oa[ni][1]*f0);
        *(float2*)(Ob + (size_t)(qr+8)*DHEAD + col) = make_float2(oa[ni][2]*f1, oa[ni][3]*f1);
    }
}

// ================= launch =================
extern "C" void kernel_launch(void* const* d_in, const int* in_sizes, int n_in,
                              void* d_out, int out_size)
{
    const float* x  = (const float*)d_in[0];
    const float* Wq = (const float*)d_in[1];
    const float* bq = (const float*)d_in[2];
    const float* Wk = (const float*)d_in[3];
    const float* bk = (const float*)d_in[4];
    const float* Wv = (const float*)d_in[5];
    const float* bv = (const float*)d_in[6];

    float* out = (float*)d_out;
    float* gkv;
    cudaGetSymbolAddress((void**)&gkv, g_KV);

    float *Kout, *Vout;
    if (out_size >= 3 * NPER) { Kout = out + NPER; Vout = out + 2 * NPER; }
    else                      { Kout = gkv;        Vout = gkv + NPER;     }

    cudaFuncSetAttribute(proj_q_kernel,  cudaFuncAttributeMaxDynamicSharedMemorySize, SMEM_Q);
    cudaFuncSetAttribute(proj_kv_kernel, cudaFuncAttributeMaxDynamicSharedMemorySize, SMEM_KV);
    cudaFuncSetAttribute(flash_kernel,   cudaFuncAttributeMaxDynamicSharedMemorySize, SMEM_FLASH);

    convert_kernel<<<(XU + 3*WU) / (256*8), 256>>>(x, Wq, Wk, Wv);
    proj_kv_kernel<<<128, 256, SMEM_KV>>>(bk, bv, Kout, Vout);
    proj_q_kernel<<<128, 256, SMEM_Q>>>(bq);
    flash_kernel<<<dim3(SEQ/128, BATCH), 256, SMEM_FLASH>>>(out);
}